// round 5
// baseline (speedup 1.0000x reference)
#include <cuda_runtime.h>
#include <cstdint>

// Problem constants
#define BATCH 32
#define NTOK  1024
#define FDIM  512
#define GRP   16
#define SEQ   64
#define DDIM  256
#define WIN   32
#define OCH   512
#define TOUT  993          // NTOK - WIN + 1
#define KTOT  (WIN * DDIM) // 8192
#define NEG_SLOPE 0.2f

// Scratch (device globals; no allocs allowed)
__device__ float g_mid[BATCH * NTOK * DDIM];          // 32 MB, tf32-rounded
__device__ float g_cwT[OCH * KTOT];                   // 16 MB, conv_w transposed [O][K], tf32
__device__ float g_wr [GRP * FDIM * DDIM];            // 8 MB, W tf32-rounded

__device__ __forceinline__ unsigned f2tf(float v) {
    unsigned r;
    asm("cvt.rna.tf32.f32 %0, %1;" : "=r"(r) : "f"(v));
    return r;
}

__device__ __forceinline__ void cp16(unsigned smem, const float* g, int sz) {
    asm volatile("cp.async.ca.shared.global [%0], [%1], 16, %2;\n"
                 :: "r"(smem), "l"(g), "r"(sz));
}

__device__ __forceinline__ void ldsm4(unsigned* r, unsigned addr) {
    asm volatile("ldmatrix.sync.aligned.m8n8.x4.shared.b16 {%0,%1,%2,%3}, [%4];"
                 : "=r"(r[0]), "=r"(r[1]), "=r"(r[2]), "=r"(r[3]) : "r"(addr));
}

__device__ __forceinline__ void mma_tf32(float* c, const unsigned* a, const unsigned* b) {
    asm volatile(
        "mma.sync.aligned.m16n8k8.row.col.f32.tf32.tf32.f32 "
        "{%0,%1,%2,%3}, {%4,%5,%6,%7}, {%8,%9}, {%0,%1,%2,%3};\n"
        : "+f"(c[0]), "+f"(c[1]), "+f"(c[2]), "+f"(c[3])
        : "r"(a[0]), "r"(a[1]), "r"(a[2]), "r"(a[3]), "r"(b[0]), "r"(b[1]));
}

// ===========================================================================
// Pre-pass kernels
// ===========================================================================
__global__ __launch_bounds__(256)
void cvt_w_kernel(const float* __restrict__ W) {
    int i = (blockIdx.x * 256 + threadIdx.x) * 4;
    float4 v = *(const float4*)(W + i);
    unsigned* o = (unsigned*)(g_wr + i);
    o[0] = f2tf(v.x); o[1] = f2tf(v.y); o[2] = f2tf(v.z); o[3] = f2tf(v.w);
}

// transpose conv_w [K=8192][O=512] -> g_cwT [O=512][K=8192], tf32-rounded
__global__ __launch_bounds__(256)
void trans_cw_kernel(const float* __restrict__ cw) {
    __shared__ float tile[32][33];
    const int o0 = blockIdx.x * 32;
    const int k0 = blockIdx.y * 32;
    const int tx = threadIdx.x & 31;
    const int ty = threadIdx.x >> 5;
#pragma unroll
    for (int j = 0; j < 4; j++) {
        int k = ty + j * 8;
        tile[k][tx] = __uint_as_float(f2tf(cw[(long)(k0 + k) * OCH + o0 + tx]));
    }
    __syncthreads();
#pragma unroll
    for (int j = 0; j < 4; j++) {
        int o = ty + j * 8;
        g_cwT[(long)(o0 + o) * KTOT + k0 + tx] = tile[tx][o];
    }
}

// ===========================================================================
// Kernel 1: gather + grouped GEMM via mma.sync tf32 (m16n8k8)
// CTA 128x128x16, 8 warps (4m x 2n), warp 32x64. M=2048, K=512, N=256.
// ===========================================================================
#define BK 16
#define AST 20
#define BST 136

__global__ __launch_bounds__(256, 2)
void gemm1_mma_kernel(const float* __restrict__ x, const int* __restrict__ idx,
                      const float* __restrict__ bias) {
    const int grp = blockIdx.z;
    const int m0  = blockIdx.y * 128;
    const int n0  = blockIdx.x * 128;
    const int tid  = threadIdx.x;
    const int lane = tid & 31;
    const int warp = tid >> 5;
    const int wm = warp >> 1;
    const int wn = warp & 1;
    const int gi = lane >> 2;
    const int tl = lane & 3;

    __shared__ float As[2][128][AST];
    __shared__ float Bs[2][BK][BST];
    __shared__ int   rowbase[128];

    if (tid < 128) {
        int m  = m0 + tid;
        int bb = m >> 6;
        int s  = m & 63;
        rowbase[tid] = bb * NTOK + idx[grp * SEQ + s];
    }
    __syncthreads();

    const int am0 = tid >> 2;
    const int ak0 = (tid & 3) * 4;
    const int bn0 = (tid & 31) * 4;
    const int bk0 = tid >> 5;

    const long arow0 = (long)rowbase[am0] * FDIM;
    const long arow1 = (long)rowbase[am0 + 64] * FDIM;
    const float* Bsrc = g_wr + (long)grp * FDIM * DDIM;

    unsigned as_base = (unsigned)__cvta_generic_to_shared(&As[0][0][0]);
    unsigned bs_base = (unsigned)__cvta_generic_to_shared(&Bs[0][0][0]);
    const unsigned as_stage = 128 * AST * 4;
    const unsigned bs_stage = BK * BST * 4;

    float acc[2][8][4];
#pragma unroll
    for (int mt = 0; mt < 2; mt++)
#pragma unroll
        for (int nt = 0; nt < 8; nt++)
#pragma unroll
            for (int i = 0; i < 4; i++) acc[mt][nt][i] = 0.f;

    const int NSTAGE = FDIM / BK;   // 32

    {
        cp16(as_base + (am0 * AST + ak0) * 4, x + arow0 + ak0, 16);
        cp16(as_base + ((am0 + 64) * AST + ak0) * 4, x + arow1 + ak0, 16);
#pragma unroll
        for (int it = 0; it < 2; it++) {
            int k = bk0 + it * 8;
            cp16(bs_base + (k * BST + bn0) * 4, Bsrc + (long)k * DDIM + n0 + bn0, 16);
        }
        asm volatile("cp.async.commit_group;\n");
    }

#pragma unroll 1
    for (int s = 0; s < NSTAGE; s++) {
        asm volatile("cp.async.wait_group 0;\n");
        __syncthreads();

        if (s + 1 < NSTAGE) {
            const int ks = (s + 1) * BK;
            const unsigned ab  = as_base + ((s + 1) & 1) * as_stage;
            const unsigned bb2 = bs_base + ((s + 1) & 1) * bs_stage;
            cp16(ab + (am0 * AST + ak0) * 4, x + arow0 + ks + ak0, 16);
            cp16(ab + ((am0 + 64) * AST + ak0) * 4, x + arow1 + ks + ak0, 16);
#pragma unroll
            for (int it = 0; it < 2; it++) {
                int k = bk0 + it * 8;
                cp16(bb2 + (k * BST + bn0) * 4, Bsrc + (long)(ks + k) * DDIM + n0 + bn0, 16);
            }
            asm volatile("cp.async.commit_group;\n");
        }

        const int cur = s & 1;
#pragma unroll
        for (int kk = 0; kk < BK; kk += 8) {
            unsigned af[2][4];
#pragma unroll
            for (int mt = 0; mt < 2; mt++) {
                int rm = wm * 32 + mt * 16;
                af[mt][0] = f2tf(As[cur][rm + gi     ][kk + tl    ]);
                af[mt][1] = f2tf(As[cur][rm + gi + 8 ][kk + tl    ]);
                af[mt][2] = f2tf(As[cur][rm + gi     ][kk + tl + 4]);
                af[mt][3] = f2tf(As[cur][rm + gi + 8 ][kk + tl + 4]);
            }
            unsigned bf[8][2];
#pragma unroll
            for (int nt = 0; nt < 8; nt++) {
                int cn = wn * 64 + nt * 8;
                bf[nt][0] = __float_as_uint(Bs[cur][kk + tl    ][cn + gi]);
                bf[nt][1] = __float_as_uint(Bs[cur][kk + tl + 4][cn + gi]);
            }
#pragma unroll
            for (int mt = 0; mt < 2; mt++)
#pragma unroll
                for (int nt = 0; nt < 8; nt++)
                    mma_tf32(acc[mt][nt], af[mt], bf[nt]);
        }
        __syncthreads();
    }

#pragma unroll
    for (int mt = 0; mt < 2; mt++) {
        int r0 = m0 + wm * 32 + mt * 16 + gi;
        int r1 = r0 + 8;
#pragma unroll
        for (int nt = 0; nt < 8; nt++) {
            int c = n0 + wn * 64 + nt * 8 + 2 * tl;
            float2 bv = *(const float2*)(bias + grp * DDIM + c);
            {
                int bb = r0 >> 6, s = r0 & 63;
                unsigned* dst = (unsigned*)(g_mid + ((long)(bb * NTOK + grp * SEQ + s)) * DDIM + c);
                dst[0] = f2tf(acc[mt][nt][0] + bv.x);
                dst[1] = f2tf(acc[mt][nt][1] + bv.y);
            }
            {
                int bb = r1 >> 6, s = r1 & 63;
                unsigned* dst = (unsigned*)(g_mid + ((long)(bb * NTOK + grp * SEQ + s)) * DDIM + c);
                dst[0] = f2tf(acc[mt][nt][2] + bv.x);
                dst[1] = f2tf(acc[mt][nt][3] + bv.y);
            }
        }
    }
}

// ===========================================================================
// Kernel 2: conv1d as implicit GEMM, mma.sync tf32 + ldmatrix fragments
//   CTA 128x128, 8 warps (2m x 4n), warp 64x32, BK=32, 3-stage cp.async.
//   Single __syncthreads per stage (CUTLASS multistage pattern).
//   Rows are 128B; 16B chunks XOR-swizzled: chunk' = chunk ^ (row & 7).
// ===========================================================================
#define BKC 32
#define TILE_B 16384                 // 128 * 32 * 4
#define SM_A 0
#define SM_B (3 * TILE_B)
#define SM_TOTAL_CONV (6 * TILE_B)   // 96 KB

__global__ __launch_bounds__(256, 2)
void conv_mma_kernel(const float* __restrict__ cb, float* __restrict__ y) {
    extern __shared__ __align__(128) char smem[];
    unsigned smem_base;
    asm("{ .reg .u64 t; cvta.to.shared.u64 t, %1; cvt.u32.u64 %0, t; }"
        : "=r"(smem_base) : "l"(smem));

    const int b  = blockIdx.z;
    const int t0 = blockIdx.y * 128;
    const int n0 = blockIdx.x * 128;
    const int tid  = threadIdx.x;
    const int lane = tid & 31;
    const int warp = tid >> 5;
    const int wm = warp & 1;         // 0..1 -> m offset wm*64
    const int wn = warp >> 1;        // 0..3 -> n offset wn*32
    const int gi = lane >> 2;
    const int tl = lane & 3;
    const int grp8 = lane >> 3;      // 0..3
    const int r8   = lane & 7;

    const float* midb = g_mid + (long)b * NTOK * DDIM;

    float acc[4][4][4];
#pragma unroll
    for (int mt = 0; mt < 4; mt++)
#pragma unroll
        for (int nt = 0; nt < 4; nt++)
#pragma unroll
            for (int i = 0; i < 4; i++) acc[mt][nt][i] = 0.f;

    const int NS = KTOT / BKC;   // 256

    auto load_stage = [&](int it) {
        const int ks = it * BKC;
        const int w  = ks >> 8;
        const int d0 = ks & 255;
        const int buf = it % 3;
        const unsigned abase = smem_base + SM_A + buf * TILE_B;
        const unsigned bbase = smem_base + SM_B + buf * TILE_B;
#pragma unroll
        for (int i = 0; i < 4; i++) {
            int c   = tid + i * 256;        // 0..1023
            int row = c >> 3;
            int ch  = c & 7;
            int t   = t0 + row + w;
            cp16(abase + row * 128 + ((ch ^ (row & 7)) * 16),
                 midb + (long)t * DDIM + d0 + ch * 4, (t < NTOK) ? 16 : 0);
        }
#pragma unroll
        for (int i = 0; i < 4; i++) {
            int c   = tid + i * 256;
            int row = c >> 3;
            int ch  = c & 7;
            cp16(bbase + row * 128 + ((ch ^ (row & 7)) * 16),
                 g_cwT + (long)(n0 + row) * KTOT + ks + ch * 4, 16);
        }
        asm volatile("cp.async.commit_group;\n");
    };

    load_stage(0);
    load_stage(1);

#pragma unroll 1
    for (int s = 0; s < NS; s++) {
        if (s + 1 < NS) asm volatile("cp.async.wait_group 1;\n");
        else            asm volatile("cp.async.wait_group 0;\n");
        __syncthreads();

        if (s + 2 < NS) load_stage(s + 2);

        const int buf = s % 3;
        const unsigned abase = smem_base + SM_A + buf * TILE_B;
        const unsigned bbase = smem_base + SM_B + buf * TILE_B;

#pragma unroll
        for (int kk = 0; kk < BKC; kk += 8) {
            const int kc = kk >> 2;
            unsigned af[4][4];
#pragma unroll
            for (int mt = 0; mt < 4; mt++) {
                int row = wm * 64 + mt * 16 + (grp8 & 1) * 8 + r8;
                int ch  = kc + (grp8 >> 1);
                ldsm4(af[mt], abase + row * 128 + ((ch ^ (row & 7)) * 16));
            }
            unsigned bf[2][4];   // bf[q]: {b0,b1} of n-block 2q, {b0,b1} of 2q+1
#pragma unroll
            for (int q = 0; q < 2; q++) {
                int row = wn * 32 + q * 16 + (grp8 >> 1) * 8 + r8;
                int ch  = kc + (grp8 & 1);
                ldsm4(bf[q], bbase + row * 128 + ((ch ^ (row & 7)) * 16));
            }
#pragma unroll
            for (int mt = 0; mt < 4; mt++)
#pragma unroll
                for (int nt = 0; nt < 4; nt++)
                    mma_tf32(acc[mt][nt], af[mt], &bf[nt >> 1][(nt & 1) * 2]);
        }
        // no trailing __syncthreads: next iteration's top sync protects the
        // 3-buffer ring (writes at s+2 target buf (s-1)%3, read finished at s-1)
    }

    // epilogue: bias + leaky relu
#pragma unroll
    for (int mt = 0; mt < 4; mt++) {
        int r0 = t0 + wm * 64 + mt * 16 + gi;
        int r1 = r0 + 8;
#pragma unroll
        for (int nt = 0; nt < 4; nt++) {
            int c = n0 + wn * 32 + nt * 8 + 2 * tl;
            float2 bv = *(const float2*)(cb + c);
            if (r0 < TOUT) {
                float v0 = acc[mt][nt][0] + bv.x;
                float v1 = acc[mt][nt][1] + bv.y;
                v0 = (v0 >= 0.f) ? v0 : NEG_SLOPE * v0;
                v1 = (v1 >= 0.f) ? v1 : NEG_SLOPE * v1;
                *(float2*)(y + ((long)b * TOUT + r0) * OCH + c) = make_float2(v0, v1);
            }
            if (r1 < TOUT) {
                float v2 = acc[mt][nt][2] + bv.x;
                float v3 = acc[mt][nt][3] + bv.y;
                v2 = (v2 >= 0.f) ? v2 : NEG_SLOPE * v2;
                v3 = (v3 >= 0.f) ? v3 : NEG_SLOPE * v3;
                *(float2*)(y + ((long)b * TOUT + r1) * OCH + c) = make_float2(v2, v3);
            }
        }
    }
}

// ===========================================================================
extern "C" void kernel_launch(void* const* d_in, const int* in_sizes, int n_in,
                              void* d_out, int out_size) {
    const float* x    = (const float*)d_in[0];
    const int*   idx  = (const int*)  d_in[1];
    const float* W    = (const float*)d_in[2];
    const float* bias = (const float*)d_in[3];
    const float* cw   = (const float*)d_in[4];
    const float* cb   = (const float*)d_in[5];
    float* y = (float*)d_out;

    cudaFuncSetAttribute(conv_mma_kernel,
                         cudaFuncAttributeMaxDynamicSharedMemorySize, SM_TOTAL_CONV);

    cvt_w_kernel<<<(GRP * FDIM * DDIM) / (256 * 4), 256>>>(W);
    trans_cw_kernel<<<dim3(OCH / 32, KTOT / 32), 256>>>(cw);

    dim3 grid1(DDIM / 128, (BATCH * SEQ) / 128, GRP);   // (2, 16, 16)
    gemm1_mma_kernel<<<grid1, 256>>>(x, idx, bias);

    dim3 grid2(OCH / 128, NTOK / 128, BATCH);           // (4, 8, 32)
    conv_mma_kernel<<<grid2, 256, SM_TOTAL_CONV>>>(cb, y);
}

// round 6
// speedup vs baseline: 1.0109x; 1.0109x over previous
#include <cuda_runtime.h>
#include <cstdint>

// Problem constants
#define BATCH 32
#define NTOK  1024
#define FDIM  512
#define GRP   16
#define SEQ   64
#define DDIM  256
#define WIN   32
#define OCH   512
#define TOUT  993          // NTOK - WIN + 1
#define KTOT  (WIN * DDIM) // 8192
#define NEG_SLOPE 0.2f

// Scratch (device globals; no allocs allowed)
__device__ float g_mid[BATCH * NTOK * DDIM];          // 32 MB, tf32-rounded
__device__ float g_cwT[OCH * KTOT];                   // 16 MB, conv_w transposed [O][K], tf32
__device__ float g_wr [GRP * FDIM * DDIM];            // 8 MB, W tf32-rounded

__device__ __forceinline__ unsigned f2tf(float v) {
    unsigned r;
    asm("cvt.rna.tf32.f32 %0, %1;" : "=r"(r) : "f"(v));
    return r;
}

__device__ __forceinline__ void cp16(unsigned smem, const float* g, int sz) {
    asm volatile("cp.async.ca.shared.global [%0], [%1], 16, %2;\n"
                 :: "r"(smem), "l"(g), "r"(sz));
}

__device__ __forceinline__ void ldsm4(unsigned* r, unsigned addr) {
    asm volatile("ldmatrix.sync.aligned.m8n8.x4.shared.b16 {%0,%1,%2,%3}, [%4];"
                 : "=r"(r[0]), "=r"(r[1]), "=r"(r[2]), "=r"(r[3]) : "r"(addr));
}

__device__ __forceinline__ void mma_tf32(float* c, const unsigned* a, const unsigned* b) {
    asm volatile(
        "mma.sync.aligned.m16n8k8.row.col.f32.tf32.tf32.f32 "
        "{%0,%1,%2,%3}, {%4,%5,%6,%7}, {%8,%9}, {%0,%1,%2,%3};\n"
        : "+f"(c[0]), "+f"(c[1]), "+f"(c[2]), "+f"(c[3])
        : "r"(a[0]), "r"(a[1]), "r"(a[2]), "r"(a[3]), "r"(b[0]), "r"(b[1]));
}

// ===========================================================================
// Pre-pass kernels
// ===========================================================================
__global__ __launch_bounds__(256)
void cvt_w_kernel(const float* __restrict__ W) {
    int i = (blockIdx.x * 256 + threadIdx.x) * 4;
    float4 v = *(const float4*)(W + i);
    unsigned* o = (unsigned*)(g_wr + i);
    o[0] = f2tf(v.x); o[1] = f2tf(v.y); o[2] = f2tf(v.z); o[3] = f2tf(v.w);
}

// transpose conv_w [K=8192][O=512] -> g_cwT [O=512][K=8192], tf32-rounded
__global__ __launch_bounds__(256)
void trans_cw_kernel(const float* __restrict__ cw) {
    __shared__ float tile[32][33];
    const int o0 = blockIdx.x * 32;
    const int k0 = blockIdx.y * 32;
    const int tx = threadIdx.x & 31;
    const int ty = threadIdx.x >> 5;
#pragma unroll
    for (int j = 0; j < 4; j++) {
        int k = ty + j * 8;
        tile[k][tx] = __uint_as_float(f2tf(cw[(long)(k0 + k) * OCH + o0 + tx]));
    }
    __syncthreads();
#pragma unroll
    for (int j = 0; j < 4; j++) {
        int o = ty + j * 8;
        g_cwT[(long)(o0 + o) * KTOT + k0 + tx] = tile[tx][o];
    }
}

// ===========================================================================
// Kernel 1: gather + grouped GEMM via mma.sync tf32 (m16n8k8)
// CTA 128x128x16, 8 warps (4m x 2n), warp 32x64. M=2048, K=512, N=256.
// ===========================================================================
#define BK 16
#define AST 20
#define BST 136

__global__ __launch_bounds__(256, 2)
void gemm1_mma_kernel(const float* __restrict__ x, const int* __restrict__ idx,
                      const float* __restrict__ bias) {
    const int grp = blockIdx.z;
    const int m0  = blockIdx.y * 128;
    const int n0  = blockIdx.x * 128;
    const int tid  = threadIdx.x;
    const int lane = tid & 31;
    const int warp = tid >> 5;
    const int wm = warp >> 1;
    const int wn = warp & 1;
    const int gi = lane >> 2;
    const int tl = lane & 3;

    __shared__ float As[2][128][AST];
    __shared__ float Bs[2][BK][BST];
    __shared__ int   rowbase[128];

    if (tid < 128) {
        int m  = m0 + tid;
        int bb = m >> 6;
        int s  = m & 63;
        rowbase[tid] = bb * NTOK + idx[grp * SEQ + s];
    }
    __syncthreads();

    const int am0 = tid >> 2;
    const int ak0 = (tid & 3) * 4;
    const int bn0 = (tid & 31) * 4;
    const int bk0 = tid >> 5;

    const long arow0 = (long)rowbase[am0] * FDIM;
    const long arow1 = (long)rowbase[am0 + 64] * FDIM;
    const float* Bsrc = g_wr + (long)grp * FDIM * DDIM;

    unsigned as_base = (unsigned)__cvta_generic_to_shared(&As[0][0][0]);
    unsigned bs_base = (unsigned)__cvta_generic_to_shared(&Bs[0][0][0]);
    const unsigned as_stage = 128 * AST * 4;
    const unsigned bs_stage = BK * BST * 4;

    float acc[2][8][4];
#pragma unroll
    for (int mt = 0; mt < 2; mt++)
#pragma unroll
        for (int nt = 0; nt < 8; nt++)
#pragma unroll
            for (int i = 0; i < 4; i++) acc[mt][nt][i] = 0.f;

    const int NSTAGE = FDIM / BK;   // 32

    {
        cp16(as_base + (am0 * AST + ak0) * 4, x + arow0 + ak0, 16);
        cp16(as_base + ((am0 + 64) * AST + ak0) * 4, x + arow1 + ak0, 16);
#pragma unroll
        for (int it = 0; it < 2; it++) {
            int k = bk0 + it * 8;
            cp16(bs_base + (k * BST + bn0) * 4, Bsrc + (long)k * DDIM + n0 + bn0, 16);
        }
        asm volatile("cp.async.commit_group;\n");
    }

#pragma unroll 1
    for (int s = 0; s < NSTAGE; s++) {
        asm volatile("cp.async.wait_group 0;\n");
        __syncthreads();

        if (s + 1 < NSTAGE) {
            const int ks = (s + 1) * BK;
            const unsigned ab  = as_base + ((s + 1) & 1) * as_stage;
            const unsigned bb2 = bs_base + ((s + 1) & 1) * bs_stage;
            cp16(ab + (am0 * AST + ak0) * 4, x + arow0 + ks + ak0, 16);
            cp16(ab + ((am0 + 64) * AST + ak0) * 4, x + arow1 + ks + ak0, 16);
#pragma unroll
            for (int it = 0; it < 2; it++) {
                int k = bk0 + it * 8;
                cp16(bb2 + (k * BST + bn0) * 4, Bsrc + (long)(ks + k) * DDIM + n0 + bn0, 16);
            }
            asm volatile("cp.async.commit_group;\n");
        }

        const int cur = s & 1;
#pragma unroll
        for (int kk = 0; kk < BK; kk += 8) {
            unsigned af[2][4];
#pragma unroll
            for (int mt = 0; mt < 2; mt++) {
                int rm = wm * 32 + mt * 16;
                af[mt][0] = f2tf(As[cur][rm + gi     ][kk + tl    ]);
                af[mt][1] = f2tf(As[cur][rm + gi + 8 ][kk + tl    ]);
                af[mt][2] = f2tf(As[cur][rm + gi     ][kk + tl + 4]);
                af[mt][3] = f2tf(As[cur][rm + gi + 8 ][kk + tl + 4]);
            }
            unsigned bf[8][2];
#pragma unroll
            for (int nt = 0; nt < 8; nt++) {
                int cn = wn * 64 + nt * 8;
                bf[nt][0] = __float_as_uint(Bs[cur][kk + tl    ][cn + gi]);
                bf[nt][1] = __float_as_uint(Bs[cur][kk + tl + 4][cn + gi]);
            }
#pragma unroll
            for (int mt = 0; mt < 2; mt++)
#pragma unroll
                for (int nt = 0; nt < 8; nt++)
                    mma_tf32(acc[mt][nt], af[mt], bf[nt]);
        }
        __syncthreads();
    }

#pragma unroll
    for (int mt = 0; mt < 2; mt++) {
        int r0 = m0 + wm * 32 + mt * 16 + gi;
        int r1 = r0 + 8;
#pragma unroll
        for (int nt = 0; nt < 8; nt++) {
            int c = n0 + wn * 64 + nt * 8 + 2 * tl;
            float2 bv = *(const float2*)(bias + grp * DDIM + c);
            {
                int bb = r0 >> 6, s = r0 & 63;
                unsigned* dst = (unsigned*)(g_mid + ((long)(bb * NTOK + grp * SEQ + s)) * DDIM + c);
                dst[0] = f2tf(acc[mt][nt][0] + bv.x);
                dst[1] = f2tf(acc[mt][nt][1] + bv.y);
            }
            {
                int bb = r1 >> 6, s = r1 & 63;
                unsigned* dst = (unsigned*)(g_mid + ((long)(bb * NTOK + grp * SEQ + s)) * DDIM + c);
                dst[0] = f2tf(acc[mt][nt][2] + bv.x);
                dst[1] = f2tf(acc[mt][nt][3] + bv.y);
            }
        }
    }
}

// ===========================================================================
// Kernel 2: conv1d as implicit GEMM, mma.sync tf32 + ldmatrix fragments
//   CTA 128x128, 4 warps (2m x 2n), warp 64x64, BK=32, 3-stage cp.async.
//   Fragment DOUBLE-BUFFERING: kslice j+1's LDSMs issue before kslice j's MMAs.
//   Rows are 128B; 16B chunks XOR-swizzled: chunk' = chunk ^ (row & 7).
// ===========================================================================
#define BKC 32
#define TILE_B 16384                 // 128 * 32 * 4
#define SM_A 0
#define SM_B (3 * TILE_B)
#define SM_TOTAL_CONV (6 * TILE_B)   // 96 KB

__global__ __launch_bounds__(128, 2)
void conv_mma_kernel(const float* __restrict__ cb, float* __restrict__ y) {
    extern __shared__ __align__(128) char smem[];
    unsigned smem_base;
    asm("{ .reg .u64 t; cvta.to.shared.u64 t, %1; cvt.u32.u64 %0, t; }"
        : "=r"(smem_base) : "l"(smem));

    const int b  = blockIdx.z;
    const int t0 = blockIdx.y * 128;
    const int n0 = blockIdx.x * 128;
    const int tid  = threadIdx.x;
    const int lane = tid & 31;
    const int warp = tid >> 5;
    const int wm = warp >> 1;        // 0..1 -> m offset wm*64
    const int wn = warp & 1;         // 0..1 -> n offset wn*64
    const int gi = lane >> 2;
    const int tl = lane & 3;
    const int grp8 = lane >> 3;      // 0..3
    const int r8   = lane & 7;

    const float* midb = g_mid + (long)b * NTOK * DDIM;

    float acc[4][8][4];
#pragma unroll
    for (int mt = 0; mt < 4; mt++)
#pragma unroll
        for (int nt = 0; nt < 8; nt++)
#pragma unroll
            for (int i = 0; i < 4; i++) acc[mt][nt][i] = 0.f;

    const int NS = KTOT / BKC;   // 256

    auto load_stage = [&](int it) {
        const int ks = it * BKC;
        const int w  = ks >> 8;
        const int d0 = ks & 255;
        const int buf = it % 3;
        const unsigned abase = smem_base + SM_A + buf * TILE_B;
        const unsigned bbase = smem_base + SM_B + buf * TILE_B;
#pragma unroll
        for (int i = 0; i < 8; i++) {
            int c   = tid + i * 128;        // 0..1023
            int row = c >> 3;
            int ch  = c & 7;
            int t   = t0 + row + w;
            cp16(abase + row * 128 + ((ch ^ (row & 7)) * 16),
                 midb + (long)t * DDIM + d0 + ch * 4, (t < NTOK) ? 16 : 0);
        }
#pragma unroll
        for (int i = 0; i < 8; i++) {
            int c   = tid + i * 128;
            int row = c >> 3;
            int ch  = c & 7;
            cp16(bbase + row * 128 + ((ch ^ (row & 7)) * 16),
                 g_cwT + (long)(n0 + row) * KTOT + ks + ch * 4, 16);
        }
        asm volatile("cp.async.commit_group;\n");
    };

    // fragment loader for one kslice (kc = kk>>2, kk in {0,8,16,24})
    auto ldfrag = [&](unsigned af[4][4], unsigned bf[4][4],
                      int kc, unsigned abase, unsigned bbase) {
#pragma unroll
        for (int mt = 0; mt < 4; mt++) {
            int row = wm * 64 + mt * 16 + (grp8 & 1) * 8 + r8;
            int ch  = kc + (grp8 >> 1);
            ldsm4(af[mt], abase + row * 128 + ((ch ^ (row & 7)) * 16));
        }
#pragma unroll
        for (int q = 0; q < 4; q++) {
            int row = wn * 64 + q * 16 + (grp8 >> 1) * 8 + r8;
            int ch  = kc + (grp8 & 1);
            ldsm4(bf[q], bbase + row * 128 + ((ch ^ (row & 7)) * 16));
        }
    };

    load_stage(0);
    load_stage(1);

    unsigned af[2][4][4];
    unsigned bf[2][4][4];

#pragma unroll 1
    for (int s = 0; s < NS; s++) {
        if (s + 1 < NS) asm volatile("cp.async.wait_group 1;\n");
        else            asm volatile("cp.async.wait_group 0;\n");
        __syncthreads();

        if (s + 2 < NS) load_stage(s + 2);

        const int buf = s % 3;
        const unsigned abase = smem_base + SM_A + buf * TILE_B;
        const unsigned bbase = smem_base + SM_B + buf * TILE_B;

        // prime kslice 0 fragments
        ldfrag(af[0], bf[0], 0, abase, bbase);

#pragma unroll
        for (int k4 = 0; k4 < 4; k4++) {
            const int cur = k4 & 1;
            // prefetch next kslice's fragments BEFORE this kslice's MMAs
            if (k4 < 3)
                ldfrag(af[cur ^ 1], bf[cur ^ 1], (k4 + 1) * 2, abase, bbase);
#pragma unroll
            for (int mt = 0; mt < 4; mt++)
#pragma unroll
                for (int nt = 0; nt < 8; nt++)
                    mma_tf32(acc[mt][nt], af[cur][mt], &bf[cur][nt >> 1][(nt & 1) * 2]);
        }
        // single sync per stage: next iteration's top sync protects the
        // 3-buffer ring (stage s+2 writes buf (s+2)%3 == (s-1)%3, whose
        // reads finished at stage s-1)
    }

    // epilogue: bias + leaky relu
#pragma unroll
    for (int mt = 0; mt < 4; mt++) {
        int r0 = t0 + wm * 64 + mt * 16 + gi;
        int r1 = r0 + 8;
#pragma unroll
        for (int nt = 0; nt < 8; nt++) {
            int c = n0 + wn * 64 + nt * 8 + 2 * tl;
            float2 bv = *(const float2*)(cb + c);
            if (r0 < TOUT) {
                float v0 = acc[mt][nt][0] + bv.x;
                float v1 = acc[mt][nt][1] + bv.y;
                v0 = (v0 >= 0.f) ? v0 : NEG_SLOPE * v0;
                v1 = (v1 >= 0.f) ? v1 : NEG_SLOPE * v1;
                *(float2*)(y + ((long)b * TOUT + r0) * OCH + c) = make_float2(v0, v1);
            }
            if (r1 < TOUT) {
                float v2 = acc[mt][nt][2] + bv.x;
                float v3 = acc[mt][nt][3] + bv.y;
                v2 = (v2 >= 0.f) ? v2 : NEG_SLOPE * v2;
                v3 = (v3 >= 0.f) ? v3 : NEG_SLOPE * v3;
                *(float2*)(y + ((long)b * TOUT + r1) * OCH + c) = make_float2(v2, v3);
            }
        }
    }
}

// ===========================================================================
extern "C" void kernel_launch(void* const* d_in, const int* in_sizes, int n_in,
                              void* d_out, int out_size) {
    const float* x    = (const float*)d_in[0];
    const int*   idx  = (const int*)  d_in[1];
    const float* W    = (const float*)d_in[2];
    const float* bias = (const float*)d_in[3];
    const float* cw   = (const float*)d_in[4];
    const float* cb   = (const float*)d_in[5];
    float* y = (float*)d_out;

    cudaFuncSetAttribute(conv_mma_kernel,
                         cudaFuncAttributeMaxDynamicSharedMemorySize, SM_TOTAL_CONV);

    cvt_w_kernel<<<(GRP * FDIM * DDIM) / (256 * 4), 256>>>(W);
    trans_cw_kernel<<<dim3(OCH / 32, KTOT / 32), 256>>>(cw);

    dim3 grid1(DDIM / 128, (BATCH * SEQ) / 128, GRP);   // (2, 16, 16)
    gemm1_mma_kernel<<<grid1, 256>>>(x, idx, bias);

    dim3 grid2(OCH / 128, NTOK / 128, BATCH);           // (4, 8, 32)
    conv_mma_kernel<<<grid2, 128, SM_TOTAL_CONV>>>(cb, y);
}

// round 7
// speedup vs baseline: 1.8831x; 1.8627x over previous
#include <cuda_runtime.h>
#include <cuda_fp16.h>
#include <cstdint>

// Problem constants
#define BATCH 32
#define NTOK  1024
#define FDIM  512
#define GRP   16
#define SEQ   64
#define DDIM  256
#define WIN   32
#define OCH   512
#define TOUT  993          // NTOK - WIN + 1
#define KTOT  (WIN * DDIM) // 8192
#define NEG_SLOPE 0.2f

// Scratch (device globals; no allocs allowed)
__device__ __half g_mid[BATCH * NTOK * DDIM];         // 16 MB, fp16 mid
__device__ __half g_cwT[OCH * KTOT];                  // 8 MB, conv_w transposed [O][K], fp16
__device__ float  g_wr [GRP * FDIM * DDIM];           // 8 MB, W tf32-rounded (for gemm1)

__device__ __forceinline__ unsigned f2tf(float v) {
    unsigned r;
    asm("cvt.rna.tf32.f32 %0, %1;" : "=r"(r) : "f"(v));
    return r;
}

__device__ __forceinline__ void cp16(unsigned smem, const void* g, int sz) {
    asm volatile("cp.async.ca.shared.global [%0], [%1], 16, %2;\n"
                 :: "r"(smem), "l"(g), "r"(sz));
}

__device__ __forceinline__ void ldsm4(unsigned* r, unsigned addr) {
    asm volatile("ldmatrix.sync.aligned.m8n8.x4.shared.b16 {%0,%1,%2,%3}, [%4];"
                 : "=r"(r[0]), "=r"(r[1]), "=r"(r[2]), "=r"(r[3]) : "r"(addr));
}

__device__ __forceinline__ void mma_tf32(float* c, const unsigned* a, const unsigned* b) {
    asm volatile(
        "mma.sync.aligned.m16n8k8.row.col.f32.tf32.tf32.f32 "
        "{%0,%1,%2,%3}, {%4,%5,%6,%7}, {%8,%9}, {%0,%1,%2,%3};\n"
        : "+f"(c[0]), "+f"(c[1]), "+f"(c[2]), "+f"(c[3])
        : "r"(a[0]), "r"(a[1]), "r"(a[2]), "r"(a[3]), "r"(b[0]), "r"(b[1]));
}

__device__ __forceinline__ void mma_f16(float* c, const unsigned* a, const unsigned* b) {
    asm volatile(
        "mma.sync.aligned.m16n8k16.row.col.f32.f16.f16.f32 "
        "{%0,%1,%2,%3}, {%4,%5,%6,%7}, {%8,%9}, {%0,%1,%2,%3};\n"
        : "+f"(c[0]), "+f"(c[1]), "+f"(c[2]), "+f"(c[3])
        : "r"(a[0]), "r"(a[1]), "r"(a[2]), "r"(a[3]), "r"(b[0]), "r"(b[1]));
}

// ===========================================================================
// Pre-pass kernels
// ===========================================================================
__global__ __launch_bounds__(256)
void cvt_w_kernel(const float* __restrict__ W) {
    int i = (blockIdx.x * 256 + threadIdx.x) * 4;
    float4 v = *(const float4*)(W + i);
    unsigned* o = (unsigned*)(g_wr + i);
    o[0] = f2tf(v.x); o[1] = f2tf(v.y); o[2] = f2tf(v.z); o[3] = f2tf(v.w);
}

// transpose conv_w [K=8192][O=512] -> g_cwT [O=512][K=8192], fp16
__global__ __launch_bounds__(256)
void trans_cw_kernel(const float* __restrict__ cw) {
    __shared__ float tile[32][33];
    const int o0 = blockIdx.x * 32;
    const int k0 = blockIdx.y * 32;
    const int tx = threadIdx.x & 31;
    const int ty = threadIdx.x >> 5;
#pragma unroll
    for (int j = 0; j < 4; j++) {
        int k = ty + j * 8;
        tile[k][tx] = cw[(long)(k0 + k) * OCH + o0 + tx];
    }
    __syncthreads();
#pragma unroll
    for (int j = 0; j < 4; j++) {
        int o = ty + j * 8;
        g_cwT[(long)(o0 + o) * KTOT + k0 + tx] = __float2half_rn(tile[tx][o]);
    }
}

// ===========================================================================
// Kernel 1: gather + grouped GEMM via mma.sync tf32 (m16n8k8)
// CTA 128x128x16, 8 warps (4m x 2n), warp 32x64. M=2048, K=512, N=256.
// Epilogue writes fp16 mid.
// ===========================================================================
#define BK 16
#define AST 20
#define BST 136

__global__ __launch_bounds__(256, 2)
void gemm1_mma_kernel(const float* __restrict__ x, const int* __restrict__ idx,
                      const float* __restrict__ bias) {
    const int grp = blockIdx.z;
    const int m0  = blockIdx.y * 128;
    const int n0  = blockIdx.x * 128;
    const int tid  = threadIdx.x;
    const int lane = tid & 31;
    const int warp = tid >> 5;
    const int wm = warp >> 1;
    const int wn = warp & 1;
    const int gi = lane >> 2;
    const int tl = lane & 3;

    __shared__ float As[2][128][AST];
    __shared__ float Bs[2][BK][BST];
    __shared__ int   rowbase[128];

    if (tid < 128) {
        int m  = m0 + tid;
        int bb = m >> 6;
        int s  = m & 63;
        rowbase[tid] = bb * NTOK + idx[grp * SEQ + s];
    }
    __syncthreads();

    const int am0 = tid >> 2;
    const int ak0 = (tid & 3) * 4;
    const int bn0 = (tid & 31) * 4;
    const int bk0 = tid >> 5;

    const long arow0 = (long)rowbase[am0] * FDIM;
    const long arow1 = (long)rowbase[am0 + 64] * FDIM;
    const float* Bsrc = g_wr + (long)grp * FDIM * DDIM;

    unsigned as_base = (unsigned)__cvta_generic_to_shared(&As[0][0][0]);
    unsigned bs_base = (unsigned)__cvta_generic_to_shared(&Bs[0][0][0]);
    const unsigned as_stage = 128 * AST * 4;
    const unsigned bs_stage = BK * BST * 4;

    float acc[2][8][4];
#pragma unroll
    for (int mt = 0; mt < 2; mt++)
#pragma unroll
        for (int nt = 0; nt < 8; nt++)
#pragma unroll
            for (int i = 0; i < 4; i++) acc[mt][nt][i] = 0.f;

    const int NSTAGE = FDIM / BK;   // 32

    {
        cp16(as_base + (am0 * AST + ak0) * 4, x + arow0 + ak0, 16);
        cp16(as_base + ((am0 + 64) * AST + ak0) * 4, x + arow1 + ak0, 16);
#pragma unroll
        for (int it = 0; it < 2; it++) {
            int k = bk0 + it * 8;
            cp16(bs_base + (k * BST + bn0) * 4, Bsrc + (long)k * DDIM + n0 + bn0, 16);
        }
        asm volatile("cp.async.commit_group;\n");
    }

#pragma unroll 1
    for (int s = 0; s < NSTAGE; s++) {
        asm volatile("cp.async.wait_group 0;\n");
        __syncthreads();

        if (s + 1 < NSTAGE) {
            const int ks = (s + 1) * BK;
            const unsigned ab  = as_base + ((s + 1) & 1) * as_stage;
            const unsigned bb2 = bs_base + ((s + 1) & 1) * bs_stage;
            cp16(ab + (am0 * AST + ak0) * 4, x + arow0 + ks + ak0, 16);
            cp16(ab + ((am0 + 64) * AST + ak0) * 4, x + arow1 + ks + ak0, 16);
#pragma unroll
            for (int it = 0; it < 2; it++) {
                int k = bk0 + it * 8;
                cp16(bb2 + (k * BST + bn0) * 4, Bsrc + (long)(ks + k) * DDIM + n0 + bn0, 16);
            }
            asm volatile("cp.async.commit_group;\n");
        }

        const int cur = s & 1;
#pragma unroll
        for (int kk = 0; kk < BK; kk += 8) {
            unsigned af[2][4];
#pragma unroll
            for (int mt = 0; mt < 2; mt++) {
                int rm = wm * 32 + mt * 16;
                af[mt][0] = f2tf(As[cur][rm + gi     ][kk + tl    ]);
                af[mt][1] = f2tf(As[cur][rm + gi + 8 ][kk + tl    ]);
                af[mt][2] = f2tf(As[cur][rm + gi     ][kk + tl + 4]);
                af[mt][3] = f2tf(As[cur][rm + gi + 8 ][kk + tl + 4]);
            }
            unsigned bf[8][2];
#pragma unroll
            for (int nt = 0; nt < 8; nt++) {
                int cn = wn * 64 + nt * 8;
                bf[nt][0] = __float_as_uint(Bs[cur][kk + tl    ][cn + gi]);
                bf[nt][1] = __float_as_uint(Bs[cur][kk + tl + 4][cn + gi]);
            }
#pragma unroll
            for (int mt = 0; mt < 2; mt++)
#pragma unroll
                for (int nt = 0; nt < 8; nt++)
                    mma_tf32(acc[mt][nt], af[mt], bf[nt]);
        }
        __syncthreads();
    }

    // epilogue: + bias, round to fp16, scatter to g_mid[b, grp*64+s, d]
#pragma unroll
    for (int mt = 0; mt < 2; mt++) {
        int r0 = m0 + wm * 32 + mt * 16 + gi;
        int r1 = r0 + 8;
#pragma unroll
        for (int nt = 0; nt < 8; nt++) {
            int c = n0 + wn * 64 + nt * 8 + 2 * tl;
            float2 bv = *(const float2*)(bias + grp * DDIM + c);
            {
                int bb = r0 >> 6, s = r0 & 63;
                __half2* dst = (__half2*)(g_mid + ((long)(bb * NTOK + grp * SEQ + s)) * DDIM + c);
                *dst = __floats2half2_rn(acc[mt][nt][0] + bv.x, acc[mt][nt][1] + bv.y);
            }
            {
                int bb = r1 >> 6, s = r1 & 63;
                __half2* dst = (__half2*)(g_mid + ((long)(bb * NTOK + grp * SEQ + s)) * DDIM + c);
                *dst = __floats2half2_rn(acc[mt][nt][2] + bv.x, acc[mt][nt][3] + bv.y);
            }
        }
    }
}

// ===========================================================================
// Kernel 2: conv1d as implicit GEMM, fp16 mma.sync m16n8k16 + ldmatrix
//   CTA 128x128, 4 warps (2m x 2n), warp 64x64, BK=64 halves, 3-stage cp.async.
//   Tiles: A [128 m][64 kh] fp16 = 16KB; B [128 n][64 kh] = 16KB. Rows 128B;
//   16B chunks (8 halves) XOR-swizzled: chunk' = chunk ^ (row & 7).
//   Fragment double-buffering across the 4 k16 slices per stage.
// ===========================================================================
#define BKH 64                       // k-halves per stage
#define TILE_B 16384                 // 128 * 64 * 2 bytes
#define SM_A 0
#define SM_B (3 * TILE_B)
#define SM_TOTAL_CONV (6 * TILE_B)   // 96 KB

__global__ __launch_bounds__(128, 2)
void conv_mma_kernel(const float* __restrict__ cb, float* __restrict__ y) {
    extern __shared__ __align__(128) char smem[];
    unsigned smem_base;
    asm("{ .reg .u64 t; cvta.to.shared.u64 t, %1; cvt.u32.u64 %0, t; }"
        : "=r"(smem_base) : "l"(smem));

    const int b  = blockIdx.z;
    const int t0 = blockIdx.y * 128;
    const int n0 = blockIdx.x * 128;
    const int tid  = threadIdx.x;
    const int lane = tid & 31;
    const int warp = tid >> 5;
    const int wm = warp >> 1;        // 0..1 -> m offset wm*64
    const int wn = warp & 1;         // 0..1 -> n offset wn*64
    const int gi = lane >> 2;
    const int tl = lane & 3;
    const int grp8 = lane >> 3;      // 0..3
    const int r8   = lane & 7;

    const __half* midb = g_mid + (long)b * NTOK * DDIM;

    float acc[4][8][4];
#pragma unroll
    for (int mt = 0; mt < 4; mt++)
#pragma unroll
        for (int nt = 0; nt < 8; nt++)
#pragma unroll
            for (int i = 0; i < 4; i++) acc[mt][nt][i] = 0.f;

    const int NS = KTOT / BKH;   // 128

    auto load_stage = [&](int it) {
        const int ks = it * BKH;         // k offset in halves
        const int w  = ks >> 8;          // window position (256 halves per w)
        const int d0 = ks & 255;         // d offset in halves (0,64,128,192)
        const int buf = it % 3;
        const unsigned abase = smem_base + SM_A + buf * TILE_B;
        const unsigned bbase = smem_base + SM_B + buf * TILE_B;
#pragma unroll
        for (int i = 0; i < 8; i++) {
            int c   = tid + i * 128;     // 0..1023
            int row = c >> 3;
            int ch  = c & 7;             // 16B chunk = 8 halves
            int t   = t0 + row + w;
            cp16(abase + row * 128 + ((ch ^ (row & 7)) * 16),
                 midb + (long)t * DDIM + d0 + ch * 8, (t < NTOK) ? 16 : 0);
        }
#pragma unroll
        for (int i = 0; i < 8; i++) {
            int c   = tid + i * 128;
            int row = c >> 3;
            int ch  = c & 7;
            cp16(bbase + row * 128 + ((ch ^ (row & 7)) * 16),
                 g_cwT + (long)(n0 + row) * KTOT + ks + ch * 8, 16);
        }
        asm volatile("cp.async.commit_group;\n");
    };

    // fragment loader for one k16 slice (kc = slice*2 chunks)
    auto ldfrag = [&](unsigned af[4][4], unsigned bf[4][4],
                      int kc, unsigned abase, unsigned bbase) {
#pragma unroll
        for (int mt = 0; mt < 4; mt++) {
            int row = wm * 64 + mt * 16 + (grp8 & 1) * 8 + r8;
            int ch  = kc + (grp8 >> 1);
            ldsm4(af[mt], abase + row * 128 + ((ch ^ (row & 7)) * 16));
        }
#pragma unroll
        for (int q = 0; q < 4; q++) {
            int row = wn * 64 + q * 16 + (grp8 >> 1) * 8 + r8;
            int ch  = kc + (grp8 & 1);
            ldsm4(bf[q], bbase + row * 128 + ((ch ^ (row & 7)) * 16));
        }
    };

    load_stage(0);
    load_stage(1);

    unsigned af[2][4][4];
    unsigned bf[2][4][4];

#pragma unroll 1
    for (int s = 0; s < NS; s++) {
        if (s + 1 < NS) asm volatile("cp.async.wait_group 1;\n");
        else            asm volatile("cp.async.wait_group 0;\n");
        __syncthreads();

        if (s + 2 < NS) load_stage(s + 2);

        const int buf = s % 3;
        const unsigned abase = smem_base + SM_A + buf * TILE_B;
        const unsigned bbase = smem_base + SM_B + buf * TILE_B;

        ldfrag(af[0], bf[0], 0, abase, bbase);

#pragma unroll
        for (int k4 = 0; k4 < 4; k4++) {          // 4 k16 slices per stage
            const int cur = k4 & 1;
            if (k4 < 3)
                ldfrag(af[cur ^ 1], bf[cur ^ 1], (k4 + 1) * 2, abase, bbase);
#pragma unroll
            for (int mt = 0; mt < 4; mt++)
#pragma unroll
                for (int nt = 0; nt < 8; nt++)
                    mma_f16(acc[mt][nt], af[cur][mt], &bf[cur][nt >> 1][(nt & 1) * 2]);
        }
        // single sync per stage (3-buffer ring protected by next top sync)
    }

    // epilogue: bias + leaky relu
#pragma unroll
    for (int mt = 0; mt < 4; mt++) {
        int r0 = t0 + wm * 64 + mt * 16 + gi;
        int r1 = r0 + 8;
#pragma unroll
        for (int nt = 0; nt < 8; nt++) {
            int c = n0 + wn * 64 + nt * 8 + 2 * tl;
            float2 bv = *(const float2*)(cb + c);
            if (r0 < TOUT) {
                float v0 = acc[mt][nt][0] + bv.x;
                float v1 = acc[mt][nt][1] + bv.y;
                v0 = (v0 >= 0.f) ? v0 : NEG_SLOPE * v0;
                v1 = (v1 >= 0.f) ? v1 : NEG_SLOPE * v1;
                *(float2*)(y + ((long)b * TOUT + r0) * OCH + c) = make_float2(v0, v1);
            }
            if (r1 < TOUT) {
                float v2 = acc[mt][nt][2] + bv.x;
                float v3 = acc[mt][nt][3] + bv.y;
                v2 = (v2 >= 0.f) ? v2 : NEG_SLOPE * v2;
                v3 = (v3 >= 0.f) ? v3 : NEG_SLOPE * v3;
                *(float2*)(y + ((long)b * TOUT + r1) * OCH + c) = make_float2(v2, v3);
            }
        }
    }
}

// ===========================================================================
extern "C" void kernel_launch(void* const* d_in, const int* in_sizes, int n_in,
                              void* d_out, int out_size) {
    const float* x    = (const float*)d_in[0];
    const int*   idx  = (const int*)  d_in[1];
    const float* W    = (const float*)d_in[2];
    const float* bias = (const float*)d_in[3];
    const float* cw   = (const float*)d_in[4];
    const float* cb   = (const float*)d_in[5];
    float* y = (float*)d_out;

    cudaFuncSetAttribute(conv_mma_kernel,
                         cudaFuncAttributeMaxDynamicSharedMemorySize, SM_TOTAL_CONV);

    cvt_w_kernel<<<(GRP * FDIM * DDIM) / (256 * 4), 256>>>(W);
    trans_cw_kernel<<<dim3(OCH / 32, KTOT / 32), 256>>>(cw);

    dim3 grid1(DDIM / 128, (BATCH * SEQ) / 128, GRP);   // (2, 16, 16)
    gemm1_mma_kernel<<<grid1, 256>>>(x, idx, bias);

    dim3 grid2(OCH / 128, NTOK / 128, BATCH);           // (4, 8, 32)
    conv_mma_kernel<<<grid2, 128, SM_TOTAL_CONV>>>(cb, y);
}